// round 9
// baseline (speedup 1.0000x reference)
#include <cuda_runtime.h>
#include <cuda_fp16.h>
#include <stdint.h>
#include <math.h>

#define BB 8
#define NN 1024
#define FIN 256
#define FOUT 256
#define HH 4
#define DD 64
#define APAD 40   // padded halves per 32-half smem row (bank-conflict-free frags)
#define RPB 4     // rows per attn block

// scratch (no cudaMalloc allowed)
__device__ __align__(16) __half g_h16[BB * NN * FOUT];  // normalized h (fp16)
__device__ float g_ei[BB * NN * HH];
__device__ float g_ej[BB * NN * HH];
__device__ __align__(16) __half g_whT[FOUT * FIN];      // fp16 hi of W^T [n][k]
__device__ __align__(16) __half g_wlT[FOUT * FIN];      // fp16 lo of W^T [n][k]

__device__ __forceinline__ void mma16816(float* d, const uint32_t* a, const uint32_t* b) {
    asm volatile(
        "mma.sync.aligned.m16n8k16.row.col.f32.f16.f16.f32 "
        "{%0,%1,%2,%3}, {%4,%5,%6,%7}, {%8,%9}, {%0,%1,%2,%3};\n"
        : "+f"(d[0]), "+f"(d[1]), "+f"(d[2]), "+f"(d[3])
        : "r"(a[0]), "r"(a[1]), "r"(a[2]), "r"(a[3]), "r"(b[0]), "r"(b[1]));
}

// ---------------------------------------------------------------------------
// Kernel 0: split fp32 W -> transposed fp16 hi/lo (256 x 64, all SMs covered)
// ---------------------------------------------------------------------------
__global__ void __launch_bounds__(64) convert_w_kernel(const float* __restrict__ W)
{
    const int idx = (blockIdx.x * 64 + threadIdx.x) * 4;   // over W [k][n]
    const float4 v = *(const float4*)(W + idx);
    const float f[4] = {v.x, v.y, v.z, v.w};
    const int k = idx >> 8;
    const int n0 = idx & 255;
    #pragma unroll
    for (int i = 0; i < 4; i++) {
        const __half h = __float2half(f[i]);
        const __half l = __float2half(f[i] - __half2float(h));
        g_whT[(n0 + i) * FIN + k] = h;
        g_wlT[(n0 + i) * FIN + k] = l;
    }
}

// ---------------------------------------------------------------------------
// Kernel 1: tensor-core split-fp16 GEMM (mma.sync.m16n8k16) + fused LN + logits
// A-tile conversion fp32 x -> fp16 hi/lo fused into the load. (R7-proven)
// ---------------------------------------------------------------------------
extern __shared__ char dynsm[];

__global__ void __launch_bounds__(256, 1) gemm_ln_tc(
    const float* __restrict__ x,
    const float* __restrict__ gamma, const float* __restrict__ beta,
    const float* __restrict__ aw)
{
    __half* Ah = (__half*)dynsm;                 // 64  x APAD
    __half* Al = Ah + 64 * APAD;
    __half* Bh = Al + 64 * APAD;                 // 256 x APAD
    __half* Bl = Bh + 256 * APAD;
    float*  hs = (float*)dynsm;                  // epilogue staging 64x256 fp32

    const int tid = threadIdx.x;
    const int wid = tid >> 5, lane = tid & 31;
    const int g = lane >> 2, q = lane & 3;
    const int m0 = (wid >> 1) * 16;
    const int n0 = (wid & 1) * 128;
    const size_t row_base = (size_t)blockIdx.x * 64;

    float acc[16][4];
    #pragma unroll
    for (int nt = 0; nt < 16; nt++)
        #pragma unroll
        for (int i = 0; i < 4; i++) acc[nt][i] = 0.0f;

    const int arow = tid >> 2, ac = (tid & 3) * 8;

    for (int kc = 0; kc < 8; kc++) {
        __syncthreads();
        {   // A chunk: 64 rows x 32 halves, converted from fp32 x in-flight
            const float* xs = x + (row_base + arow) * FIN + kc * 32 + ac;
            const float4 v0 = *(const float4*)xs;
            const float4 v1 = *(const float4*)(xs + 4);
            const float f[8] = {v0.x, v0.y, v0.z, v0.w, v1.x, v1.y, v1.z, v1.w};
            __half h[8], l[8];
            #pragma unroll
            for (int i = 0; i < 8; i++) {
                h[i] = __float2half(f[i]);
                l[i] = __float2half(f[i] - __half2float(h[i]));
            }
            __half2 hp[4], lp[4];
            #pragma unroll
            for (int i = 0; i < 4; i++) {
                hp[i] = __halves2half2(h[2 * i], h[2 * i + 1]);
                lp[i] = __halves2half2(l[2 * i], l[2 * i + 1]);
            }
            *(int4*)(Ah + arow * APAD + ac) = *(const int4*)hp;
            *(int4*)(Al + arow * APAD + ac) = *(const int4*)lp;
        }
        #pragma unroll
        for (int u = 0; u < 4; u++) {   // B chunk: 256 rows x 32 halves
            const int li = tid + u * 256;
            const int br = li >> 2, bc = (li & 3) * 8;
            *(int4*)(Bh + br * APAD + bc) = *(const int4*)(g_whT + br * FIN + kc * 32 + bc);
            *(int4*)(Bl + br * APAD + bc) = *(const int4*)(g_wlT + br * FIN + kc * 32 + bc);
        }
        __syncthreads();
        #pragma unroll
        for (int ks = 0; ks < 2; ks++) {
            const int kk = ks * 16;
            const int ar0 = (m0 + g) * APAD + kk + 2 * q;
            const int ar1 = (m0 + g + 8) * APAD + kk + 2 * q;
            uint32_t ah[4], alr[4];
            ah[0] = *(const uint32_t*)(Ah + ar0);
            ah[1] = *(const uint32_t*)(Ah + ar1);
            ah[2] = *(const uint32_t*)(Ah + ar0 + 8);
            ah[3] = *(const uint32_t*)(Ah + ar1 + 8);
            alr[0] = *(const uint32_t*)(Al + ar0);
            alr[1] = *(const uint32_t*)(Al + ar1);
            alr[2] = *(const uint32_t*)(Al + ar0 + 8);
            alr[3] = *(const uint32_t*)(Al + ar1 + 8);
            #pragma unroll
            for (int nt = 0; nt < 16; nt++) {
                const int bro = (n0 + nt * 8 + g) * APAD + kk + 2 * q;
                uint32_t bh[2], blr[2];
                bh[0]  = *(const uint32_t*)(Bh + bro);
                bh[1]  = *(const uint32_t*)(Bh + bro + 8);
                blr[0] = *(const uint32_t*)(Bl + bro);
                blr[1] = *(const uint32_t*)(Bl + bro + 8);
                mma16816(acc[nt], ah,  bh);
                mma16816(acc[nt], ah,  blr);
                mma16816(acc[nt], alr, bh);
            }
        }
    }
    __syncthreads();
    // stage accumulators to smem (fp32)
    #pragma unroll
    for (int nt = 0; nt < 16; nt++) {
        const int col = n0 + nt * 8 + 2 * q;
        *(float2*)(hs + (m0 + g) * FOUT + col)     = make_float2(acc[nt][0], acc[nt][1]);
        *(float2*)(hs + (m0 + g + 8) * FOUT + col) = make_float2(acc[nt][2], acc[nt][3]);
    }
    __syncthreads();

    // LayerNorm + logits: one warp per row, 8 rows per warp
    for (int rr = wid; rr < 64; rr += 8) {
        float v[8];
        float s = 0.0f, ss = 0.0f;
        #pragma unroll
        for (int k = 0; k < 8; k++) {
            v[k] = hs[rr * FOUT + lane + 32 * k];
            s += v[k];
            ss = fmaf(v[k], v[k], ss);
        }
        #pragma unroll
        for (int o = 16; o; o >>= 1) {
            s  += __shfl_xor_sync(0xffffffffu, s,  o);
            ss += __shfl_xor_sync(0xffffffffu, ss, o);
        }
        const float mu = s * (1.0f / FOUT);
        const float var = ss * (1.0f / FOUT) - mu * mu;
        const float rstd = rsqrtf(var + 1e-5f);

        const size_t row = row_base + rr;
        float es[4] = {0, 0, 0, 0}, ed[4] = {0, 0, 0, 0};
        #pragma unroll
        for (int k = 0; k < 8; k++) {
            const int col = lane + 32 * k;
            const float n = fmaf((v[k] - mu) * rstd, gamma[col], beta[col]);
            g_h16[row * FOUT + col] = __float2half(n);
            const int hh = k >> 1;
            const int d = lane + 32 * (k & 1);
            es[hh] = fmaf(n, aw[d], es[hh]);
            ed[hh] = fmaf(n, aw[DD + d], ed[hh]);
        }
        #pragma unroll
        for (int o = 16; o; o >>= 1) {
            #pragma unroll
            for (int hh = 0; hh < 4; hh++) {
                es[hh] += __shfl_xor_sync(0xffffffffu, es[hh], o);
                ed[hh] += __shfl_xor_sync(0xffffffffu, ed[hh], o);
            }
        }
        if (lane == 0) {
            #pragma unroll
            for (int hh = 0; hh < 4; hh++) {
                g_ei[row * HH + hh] = es[hh];
                g_ej[row * HH + hh] = ed[hh];
            }
        }
    }
}

// ---------------------------------------------------------------------------
// Kernel 2: sparse softmax+gather, R7-exact per-row pipeline, 4 rows/block
// (2048 blocks -> ~1.7 waves instead of 7; next row's adj prefetched into
// registers during the current row's gather phase).
// ---------------------------------------------------------------------------
__global__ void __launch_bounds__(256) attn_kernel(
    const float* __restrict__ adj, float* __restrict__ out)
{
    __shared__ int    nbr[NN];
    __shared__ float  sc[NN * HH];
    __shared__ float  redg[7 * 32 * 8];
    __shared__ int   wsum[8];
    __shared__ int   woff[8];
    __shared__ int   Ktot_s;
    __shared__ float red[8 * HH];
    __shared__ float sms[HH];

    const int tid = threadIdx.x;
    const int lane = tid & 31, wid = tid >> 5;
    const size_t bi0 = (size_t)blockIdx.x * RPB;

    // prefetch first row's adj
    float4 av = ((const float4*)(adj + bi0 * NN))[tid];

    #pragma unroll 1
    for (int r = 0; r < RPB; r++) {
        const size_t bi = bi0 + r;
        const size_t b  = bi >> 10;

        // ---- ordered neighbor compaction ----
        const int m0 = (av.x != 0.0f), m1 = (av.y != 0.0f),
                  m2 = (av.z != 0.0f), m3 = (av.w != 0.0f);
        const int cnt = m0 + m1 + m2 + m3;
        int pre = cnt;
        #pragma unroll
        for (int o = 1; o < 32; o <<= 1) {
            int t = __shfl_up_sync(0xffffffffu, pre, o);
            if (lane >= o) pre += t;
        }
        if (lane == 31) wsum[wid] = pre;
        __syncthreads();
        if (tid == 0) {
            int acc = 0;
            #pragma unroll
            for (int w = 0; w < 8; w++) { woff[w] = acc; acc += wsum[w]; }
            Ktot_s = acc;
        }
        __syncthreads();
        {
            int p = woff[wid] + pre - cnt;
            const int j0 = tid * 4;
            if (m0) nbr[p++] = j0;
            if (m1) nbr[p++] = j0 + 1;
            if (m2) nbr[p++] = j0 + 2;
            if (m3) nbr[p++] = j0 + 3;
        }
        __syncthreads();
        const int K = Ktot_s;

        // ---- fused scores: w = exp(leakyrelu(e_i + e_j)), accumulate sums ----
        float ei0, ei1, ei2, ei3;
        {
            const float4 e4 = ((const float4*)g_ei)[bi];
            ei0 = e4.x; ei1 = e4.y; ei2 = e4.z; ei3 = e4.w;
        }
        const float4* ej4 = (const float4*)g_ej + b * NN;
        float4* sc4 = (float4*)sc;
        float ls0 = 0, ls1 = 0, ls2 = 0, ls3 = 0;
        for (int nn = tid; nn < K; nn += 256) {
            const int j = nbr[nn];
            const float4 e4 = ej4[j];
            float t0 = ei0 + e4.x, t1 = ei1 + e4.y,
                  t2 = ei2 + e4.z, t3 = ei3 + e4.w;
            t0 = t0 > 0.0f ? t0 : 0.2f * t0;
            t1 = t1 > 0.0f ? t1 : 0.2f * t1;
            t2 = t2 > 0.0f ? t2 : 0.2f * t2;
            t3 = t3 > 0.0f ? t3 : 0.2f * t3;
            const float w0 = __expf(t0), w1 = __expf(t1),
                        w2 = __expf(t2), w3 = __expf(t3);
            sc4[nn] = make_float4(w0, w1, w2, w3);
            ls0 += w0; ls1 += w1; ls2 += w2; ls3 += w3;
        }
        #pragma unroll
        for (int o = 16; o; o >>= 1) {
            ls0 += __shfl_xor_sync(0xffffffffu, ls0, o);
            ls1 += __shfl_xor_sync(0xffffffffu, ls1, o);
            ls2 += __shfl_xor_sync(0xffffffffu, ls2, o);
            ls3 += __shfl_xor_sync(0xffffffffu, ls3, o);
        }
        if (lane == 0) {
            red[wid * 4 + 0] = ls0;
            red[wid * 4 + 1] = ls1;
            red[wid * 4 + 2] = ls2;
            red[wid * 4 + 3] = ls3;
        }
        __syncthreads();
        if (tid < 4) {
            float s = 0.0f;
            #pragma unroll
            for (int w = 0; w < 8; w++) s += red[w * 4 + tid];
            sms[tid] = s;
        }
        __syncthreads();

        // prefetch next row's adj into registers (completes during gather)
        if (r + 1 < RPB)
            av = ((const float4*)(adj + (bi + 1) * NN))[tid];

        // ---- gather-accumulate: 32 uint4 col-groups (8 halves) x 8 slices ----
        const int cg = tid & 31;
        const int sl = tid >> 5;
        const int hh = cg >> 3;
        const __half* hb = g_h16 + b * NN * FOUT;
        const float* wts = sc + hh;

        float a0 = 0, a1 = 0, a2 = 0, a3 = 0, a4 = 0, a5 = 0, a6 = 0, a7 = 0;
        for (int nn = sl; nn < K; nn += 8) {
            const int j = nbr[nn];
            const float w = wts[nn * 4];
            const uint4 hv = ((const uint4*)(hb + (size_t)j * FOUT))[cg];
            const half2* hp = (const half2*)&hv;
            const float2 f0 = __half22float2(hp[0]);
            const float2 f1 = __half22float2(hp[1]);
            const float2 f2 = __half22float2(hp[2]);
            const float2 f3 = __half22float2(hp[3]);
            a0 = fmaf(w, f0.x, a0); a1 = fmaf(w, f0.y, a1);
            a2 = fmaf(w, f1.x, a2); a3 = fmaf(w, f1.y, a3);
            a4 = fmaf(w, f2.x, a4); a5 = fmaf(w, f2.y, a5);
            a6 = fmaf(w, f3.x, a6); a7 = fmaf(w, f3.y, a7);
        }
        if (sl != 0) {
            float* rp = redg + ((sl - 1) * 32 + cg) * 8;
            ((float4*)rp)[0] = make_float4(a0, a1, a2, a3);
            ((float4*)rp)[1] = make_float4(a4, a5, a6, a7);
        }
        __syncthreads();
        if (sl == 0) {
            #pragma unroll
            for (int s = 0; s < 7; s++) {
                const float* rp = redg + (s * 32 + cg) * 8;
                const float4 p0 = ((const float4*)rp)[0];
                const float4 p1 = ((const float4*)rp)[1];
                a0 += p0.x; a1 += p0.y; a2 += p0.z; a3 += p0.w;
                a4 += p1.x; a5 += p1.y; a6 += p1.z; a7 += p1.w;
            }
            const float inv = 1.0f / sms[hh];
            float4* op = (float4*)(out + bi * FOUT + cg * 8);
            op[0] = make_float4(a0 * inv, a1 * inv, a2 * inv, a3 * inv);
            op[1] = make_float4(a4 * inv, a5 * inv, a6 * inv, a7 * inv);
        }
        // no extra barrier needed: next iteration's first barrier orders reuse
    }
}

extern "C" void kernel_launch(void* const* d_in, const int* in_sizes, int n_in,
                              void* d_out, int out_size)
{
    const float* x     = (const float*)d_in[0];
    const float* adj   = (const float*)d_in[1];
    const float* W     = (const float*)d_in[2];
    const float* gamma = (const float*)d_in[3];
    const float* beta  = (const float*)d_in[4];
    const float* a     = (const float*)d_in[5];
    float* out = (float*)d_out;

    const int dsm = 64 * FOUT * sizeof(float);   // 64KB union (>= GEMM buffers)
    cudaFuncSetAttribute(gemm_ln_tc, cudaFuncAttributeMaxDynamicSharedMemorySize, dsm);

    convert_w_kernel<<<256, 64>>>(W);
    gemm_ln_tc<<<(BB * NN) / 64, 256, dsm>>>(x, gamma, beta, a);
    attn_kernel<<<(BB * NN) / RPB, 256>>>(adj, out);
}

// round 10
// speedup vs baseline: 1.1829x; 1.1829x over previous
#include <cuda_runtime.h>
#include <cuda_fp16.h>
#include <stdint.h>
#include <math.h>

#define BB 8
#define NN 1024
#define FIN 256
#define FOUT 256
#define HH 4
#define DD 64
#define APAD 40   // padded halves per 32-half smem row (bank-conflict-free frags)

// scratch (no cudaMalloc allowed)
__device__ __align__(16) __half g_h16[BB * NN * FOUT];  // normalized h (fp16)
__device__ float g_ei[BB * NN * HH];
__device__ float g_ej[BB * NN * HH];
__device__ __align__(16) __half g_whT[FOUT * FIN];      // fp16 W^T [n][k]

__device__ __forceinline__ void mma16816(float* d, const uint32_t* a, const uint32_t* b) {
    asm volatile(
        "mma.sync.aligned.m16n8k16.row.col.f32.f16.f16.f32 "
        "{%0,%1,%2,%3}, {%4,%5,%6,%7}, {%8,%9}, {%0,%1,%2,%3};\n"
        : "+f"(d[0]), "+f"(d[1]), "+f"(d[2]), "+f"(d[3])
        : "r"(a[0]), "r"(a[1]), "r"(a[2]), "r"(a[3]), "r"(b[0]), "r"(b[1]));
}

// ---------------------------------------------------------------------------
// Kernel 0: W fp32 -> transposed fp16. 64K threads, 1 element each (latency-
// optimal: R8's 16K-thread version was a 5.2us serial-chain artifact).
// ---------------------------------------------------------------------------
__global__ void __launch_bounds__(128) convert_w_kernel(const float* __restrict__ W)
{
    const int idx = blockIdx.x * 128 + threadIdx.x;   // 65536 over W [k][n]
    const float v = W[idx];
    const int k = idx >> 8;
    const int n = idx & 255;
    g_whT[n * FIN + k] = __float2half(v);
}

// ---------------------------------------------------------------------------
// Kernel 1: tensor-core GEMM: (xh + xl) @ wh  (x split fp16, W single fp16)
// + fused LN + logits. 128 CTAs x 256 threads, CTA tile 64x256.
// ---------------------------------------------------------------------------
extern __shared__ char dynsm[];

__global__ void __launch_bounds__(256, 1) gemm_ln_tc(
    const float* __restrict__ x,
    const float* __restrict__ gamma, const float* __restrict__ beta,
    const float* __restrict__ aw)
{
    __half* Ah = (__half*)dynsm;                 // 64  x APAD
    __half* Al = Ah + 64 * APAD;
    __half* Bh = Al + 64 * APAD;                 // 256 x APAD
    float*  hs = (float*)dynsm;                  // epilogue staging 64x256 fp32

    const int tid = threadIdx.x;
    const int wid = tid >> 5, lane = tid & 31;
    const int g = lane >> 2, q = lane & 3;
    const int m0 = (wid >> 1) * 16;
    const int n0 = (wid & 1) * 128;
    const size_t row_base = (size_t)blockIdx.x * 64;

    float acc[16][4];
    #pragma unroll
    for (int nt = 0; nt < 16; nt++)
        #pragma unroll
        for (int i = 0; i < 4; i++) acc[nt][i] = 0.0f;

    const int arow = tid >> 2, ac = (tid & 3) * 8;

    for (int kc = 0; kc < 8; kc++) {
        __syncthreads();
        {   // A chunk: 64 rows x 32 halves, converted from fp32 x in-flight
            const float* xs = x + (row_base + arow) * FIN + kc * 32 + ac;
            const float4 v0 = *(const float4*)xs;
            const float4 v1 = *(const float4*)(xs + 4);
            const float f[8] = {v0.x, v0.y, v0.z, v0.w, v1.x, v1.y, v1.z, v1.w};
            __half h[8], l[8];
            #pragma unroll
            for (int i = 0; i < 8; i++) {
                h[i] = __float2half(f[i]);
                l[i] = __float2half(f[i] - __half2float(h[i]));
            }
            __half2 hp[4], lp[4];
            #pragma unroll
            for (int i = 0; i < 4; i++) {
                hp[i] = __halves2half2(h[2 * i], h[2 * i + 1]);
                lp[i] = __halves2half2(l[2 * i], l[2 * i + 1]);
            }
            *(int4*)(Ah + arow * APAD + ac) = *(const int4*)hp;
            *(int4*)(Al + arow * APAD + ac) = *(const int4*)lp;
        }
        #pragma unroll
        for (int u = 0; u < 4; u++) {   // B chunk: 256 rows x 32 halves (fp16)
            const int li = tid + u * 256;
            const int br = li >> 2, bc = (li & 3) * 8;
            *(int4*)(Bh + br * APAD + bc) = *(const int4*)(g_whT + br * FIN + kc * 32 + bc);
        }
        __syncthreads();
        #pragma unroll
        for (int ks = 0; ks < 2; ks++) {
            const int kk = ks * 16;
            const int ar0 = (m0 + g) * APAD + kk + 2 * q;
            const int ar1 = (m0 + g + 8) * APAD + kk + 2 * q;
            uint32_t ah[4], alr[4];
            ah[0] = *(const uint32_t*)(Ah + ar0);
            ah[1] = *(const uint32_t*)(Ah + ar1);
            ah[2] = *(const uint32_t*)(Ah + ar0 + 8);
            ah[3] = *(const uint32_t*)(Ah + ar1 + 8);
            alr[0] = *(const uint32_t*)(Al + ar0);
            alr[1] = *(const uint32_t*)(Al + ar1);
            alr[2] = *(const uint32_t*)(Al + ar0 + 8);
            alr[3] = *(const uint32_t*)(Al + ar1 + 8);
            #pragma unroll
            for (int nt = 0; nt < 16; nt++) {
                const int bro = (n0 + nt * 8 + g) * APAD + kk + 2 * q;
                uint32_t bh[2];
                bh[0] = *(const uint32_t*)(Bh + bro);
                bh[1] = *(const uint32_t*)(Bh + bro + 8);
                mma16816(acc[nt], ah,  bh);
                mma16816(acc[nt], alr, bh);
            }
        }
    }
    __syncthreads();
    // stage accumulators to smem (fp32)
    #pragma unroll
    for (int nt = 0; nt < 16; nt++) {
        const int col = n0 + nt * 8 + 2 * q;
        *(float2*)(hs + (m0 + g) * FOUT + col)     = make_float2(acc[nt][0], acc[nt][1]);
        *(float2*)(hs + (m0 + g + 8) * FOUT + col) = make_float2(acc[nt][2], acc[nt][3]);
    }
    __syncthreads();

    // LayerNorm + logits: one warp per row, 8 rows per warp
    for (int rr = wid; rr < 64; rr += 8) {
        float v[8];
        float s = 0.0f, ss = 0.0f;
        #pragma unroll
        for (int k = 0; k < 8; k++) {
            v[k] = hs[rr * FOUT + lane + 32 * k];
            s += v[k];
            ss = fmaf(v[k], v[k], ss);
        }
        #pragma unroll
        for (int o = 16; o; o >>= 1) {
            s  += __shfl_xor_sync(0xffffffffu, s,  o);
            ss += __shfl_xor_sync(0xffffffffu, ss, o);
        }
        const float mu = s * (1.0f / FOUT);
        const float var = ss * (1.0f / FOUT) - mu * mu;
        const float rstd = rsqrtf(var + 1e-5f);

        const size_t row = row_base + rr;
        float es[4] = {0, 0, 0, 0}, ed[4] = {0, 0, 0, 0};
        #pragma unroll
        for (int k = 0; k < 8; k++) {
            const int col = lane + 32 * k;
            const float n = fmaf((v[k] - mu) * rstd, gamma[col], beta[col]);
            g_h16[row * FOUT + col] = __float2half(n);
            const int hh = k >> 1;
            const int d = lane + 32 * (k & 1);
            es[hh] = fmaf(n, aw[d], es[hh]);
            ed[hh] = fmaf(n, aw[DD + d], ed[hh]);
        }
        #pragma unroll
        for (int o = 16; o; o >>= 1) {
            #pragma unroll
            for (int hh = 0; hh < 4; hh++) {
                es[hh] += __shfl_xor_sync(0xffffffffu, es[hh], o);
                ed[hh] += __shfl_xor_sync(0xffffffffu, ed[hh], o);
            }
        }
        if (lane == 0) {
            #pragma unroll
            for (int hh = 0; hh < 4; hh++) {
                g_ei[row * HH + hh] = es[hh];
                g_ej[row * HH + hh] = ed[hh];
            }
        }
    }
}

// ---------------------------------------------------------------------------
// Kernel 2: block-per-row sparse softmax+gather, single-pass exp.
// EXACT R7 structure (61.7us config) — grid 8192, no row loop.
// ---------------------------------------------------------------------------
__global__ void __launch_bounds__(256) attn_kernel(
    const float* __restrict__ adj, float* __restrict__ out)
{
    __shared__ int    nbr[NN];
    __shared__ float  sc[NN * HH];
    __shared__ float  redg[7 * 32 * 8];
    __shared__ int   wsum[8];
    __shared__ int   woff[8];
    __shared__ int   Ktot_s;
    __shared__ float red[8 * HH];
    __shared__ float sms[HH];

    const int tid = threadIdx.x;
    const int lane = tid & 31, wid = tid >> 5;
    const size_t bi = blockIdx.x;
    const size_t b  = bi >> 10;

    // ---- ordered neighbor compaction ----
    const float4 av = ((const float4*)(adj + bi * NN))[tid];
    const int m0 = (av.x != 0.0f), m1 = (av.y != 0.0f), m2 = (av.z != 0.0f), m3 = (av.w != 0.0f);
    int cnt = m0 + m1 + m2 + m3;
    int pre = cnt;
    #pragma unroll
    for (int o = 1; o < 32; o <<= 1) {
        int t = __shfl_up_sync(0xffffffffu, pre, o);
        if (lane >= o) pre += t;
    }
    if (lane == 31) wsum[wid] = pre;
    __syncthreads();
    if (tid == 0) {
        int acc = 0;
        #pragma unroll
        for (int w = 0; w < 8; w++) { woff[w] = acc; acc += wsum[w]; }
        Ktot_s = acc;
    }
    __syncthreads();
    {
        int p = woff[wid] + pre - cnt;
        const int j0 = tid * 4;
        if (m0) nbr[p++] = j0;
        if (m1) nbr[p++] = j0 + 1;
        if (m2) nbr[p++] = j0 + 2;
        if (m3) nbr[p++] = j0 + 3;
    }
    __syncthreads();
    const int K = Ktot_s;

    // ---- fused scores: w = exp(leakyrelu(e_i + e_j)), accumulate sums ----
    float ei0, ei1, ei2, ei3;
    {
        const float4 e4 = ((const float4*)g_ei)[bi];
        ei0 = e4.x; ei1 = e4.y; ei2 = e4.z; ei3 = e4.w;
    }
    const float4* ej4 = (const float4*)g_ej + b * NN;
    float4* sc4 = (float4*)sc;
    float ls0 = 0, ls1 = 0, ls2 = 0, ls3 = 0;
    for (int nn = tid; nn < K; nn += 256) {
        const int j = nbr[nn];
        const float4 e4 = ej4[j];
        float t0 = ei0 + e4.x, t1 = ei1 + e4.y, t2 = ei2 + e4.z, t3 = ei3 + e4.w;
        t0 = t0 > 0.0f ? t0 : 0.2f * t0;
        t1 = t1 > 0.0f ? t1 : 0.2f * t1;
        t2 = t2 > 0.0f ? t2 : 0.2f * t2;
        t3 = t3 > 0.0f ? t3 : 0.2f * t3;
        const float w0 = __expf(t0), w1 = __expf(t1), w2 = __expf(t2), w3 = __expf(t3);
        sc4[nn] = make_float4(w0, w1, w2, w3);
        ls0 += w0; ls1 += w1; ls2 += w2; ls3 += w3;
    }
    #pragma unroll
    for (int o = 16; o; o >>= 1) {
        ls0 += __shfl_xor_sync(0xffffffffu, ls0, o);
        ls1 += __shfl_xor_sync(0xffffffffu, ls1, o);
        ls2 += __shfl_xor_sync(0xffffffffu, ls2, o);
        ls3 += __shfl_xor_sync(0xffffffffu, ls3, o);
    }
    if (lane == 0) {
        red[wid * 4 + 0] = ls0;
        red[wid * 4 + 1] = ls1;
        red[wid * 4 + 2] = ls2;
        red[wid * 4 + 3] = ls3;
    }
    __syncthreads();
    if (tid < 4) {
        float s = 0.0f;
        #pragma unroll
        for (int w = 0; w < 8; w++) s += red[w * 4 + tid];
        sms[tid] = s;
    }
    __syncthreads();

    // ---- gather-accumulate: 32 uint4 col-groups (8 halves) x 8 slices ----
    const int cg = tid & 31;
    const int sl = tid >> 5;
    const int hh = cg >> 3;
    const __half* hb = g_h16 + b * NN * FOUT;
    const float* wts = sc + hh;

    float a0 = 0, a1 = 0, a2 = 0, a3 = 0, a4 = 0, a5 = 0, a6 = 0, a7 = 0;
    for (int nn = sl; nn < K; nn += 8) {
        const int j = nbr[nn];
        const float w = wts[nn * 4];
        const uint4 hv = ((const uint4*)(hb + (size_t)j * FOUT))[cg];
        const half2* hp = (const half2*)&hv;
        const float2 f0 = __half22float2(hp[0]);
        const float2 f1 = __half22float2(hp[1]);
        const float2 f2 = __half22float2(hp[2]);
        const float2 f3 = __half22float2(hp[3]);
        a0 = fmaf(w, f0.x, a0); a1 = fmaf(w, f0.y, a1);
        a2 = fmaf(w, f1.x, a2); a3 = fmaf(w, f1.y, a3);
        a4 = fmaf(w, f2.x, a4); a5 = fmaf(w, f2.y, a5);
        a6 = fmaf(w, f3.x, a6); a7 = fmaf(w, f3.y, a7);
    }
    if (sl != 0) {
        float* rp = redg + ((sl - 1) * 32 + cg) * 8;
        ((float4*)rp)[0] = make_float4(a0, a1, a2, a3);
        ((float4*)rp)[1] = make_float4(a4, a5, a6, a7);
    }
    __syncthreads();
    if (sl == 0) {
        #pragma unroll
        for (int s = 0; s < 7; s++) {
            const float* rp = redg + (s * 32 + cg) * 8;
            const float4 p0 = ((const float4*)rp)[0];
            const float4 p1 = ((const float4*)rp)[1];
            a0 += p0.x; a1 += p0.y; a2 += p0.z; a3 += p0.w;
            a4 += p1.x; a5 += p1.y; a6 += p1.z; a7 += p1.w;
        }
        const float inv = 1.0f / sms[hh];
        float4* op = (float4*)(out + bi * FOUT + cg * 8);
        op[0] = make_float4(a0 * inv, a1 * inv, a2 * inv, a3 * inv);
        op[1] = make_float4(a4 * inv, a5 * inv, a6 * inv, a7 * inv);
    }
}

extern "C" void kernel_launch(void* const* d_in, const int* in_sizes, int n_in,
                              void* d_out, int out_size)
{
    const float* x     = (const float*)d_in[0];
    const float* adj   = (const float*)d_in[1];
    const float* W     = (const float*)d_in[2];
    const float* gamma = (const float*)d_in[3];
    const float* beta  = (const float*)d_in[4];
    const float* a     = (const float*)d_in[5];
    float* out = (float*)d_out;

    const int dsm = 64 * FOUT * sizeof(float);   // 64KB union (>= GEMM buffers)
    cudaFuncSetAttribute(gemm_ln_tc, cudaFuncAttributeMaxDynamicSharedMemorySize, dsm);

    convert_w_kernel<<<512, 128>>>(W);
    gemm_ln_tc<<<(BB * NN) / 64, 256, dsm>>>(x, gamma, beta, a);
    attn_kernel<<<BB * NN, 256>>>(adj, out);
}

// round 11
// speedup vs baseline: 1.2766x; 1.0792x over previous
#include <cuda_runtime.h>
#include <cuda_fp16.h>
#include <stdint.h>
#include <math.h>

#define BB 8
#define NN 1024
#define FIN 256
#define FOUT 256
#define HH 4
#define DD 64
#define APAD 40    // padded halves per 32-half A smem row
#define BPAD 264   // padded halves per 256-half B smem row ([k][n] layout)

// scratch (no cudaMalloc allowed)
__device__ __align__(16) __half g_h16[BB * NN * FOUT];  // normalized h (fp16)
__device__ float g_ei[BB * NN * HH];
__device__ float g_ej[BB * NN * HH];

__device__ __forceinline__ void mma16816(float* d, const uint32_t* a, const uint32_t* b) {
    asm volatile(
        "mma.sync.aligned.m16n8k16.row.col.f32.f16.f16.f32 "
        "{%0,%1,%2,%3}, {%4,%5,%6,%7}, {%8,%9}, {%0,%1,%2,%3};\n"
        : "+f"(d[0]), "+f"(d[1]), "+f"(d[2]), "+f"(d[3])
        : "r"(a[0]), "r"(a[1]), "r"(a[2]), "r"(a[3]), "r"(b[0]), "r"(b[1]));
}

__device__ __forceinline__ uint32_t smem_u32(const void* p) {
    uint32_t a;
    asm("{ .reg .u64 t; cvta.to.shared.u64 t, %1; cvt.u32.u64 %0, t; }" : "=r"(a) : "l"(p));
    return a;
}

// ---------------------------------------------------------------------------
// Kernel 1: tensor-core GEMM (xh+xl)@W_fp16 + fused LN + logits.
// W fp32 is read directly (no convert kernel); B smem holds [k][n] fp16 and
// fragments come via ldmatrix.x2.trans (transpose of [k][n] == required
// col-major B fragment).
// ---------------------------------------------------------------------------
extern __shared__ char dynsm[];

__global__ void __launch_bounds__(256, 1) gemm_ln_tc(
    const float* __restrict__ x, const float* __restrict__ W,
    const float* __restrict__ gamma, const float* __restrict__ beta,
    const float* __restrict__ aw)
{
    __half* Ah = (__half*)dynsm;                 // 64 x APAD
    __half* Al = Ah + 64 * APAD;
    __half* Bs = Al + 64 * APAD;                 // 32(k) x BPAD(n)
    float*  hs = (float*)dynsm;                  // epilogue staging 64x256 fp32

    const int tid = threadIdx.x;
    const int wid = tid >> 5, lane = tid & 31;
    const int g = lane >> 2, q = lane & 3;
    const int m0 = (wid >> 1) * 16;
    const int n0 = (wid & 1) * 128;
    const size_t row_base = (size_t)blockIdx.x * 64;
    const uint32_t bbase = smem_u32(Bs);
    const int l16 = lane & 15;                   // ldmatrix row provider index

    float acc[16][4];
    #pragma unroll
    for (int nt = 0; nt < 16; nt++)
        #pragma unroll
        for (int i = 0; i < 4; i++) acc[nt][i] = 0.0f;

    const int arow = tid >> 2, ac = (tid & 3) * 8;

    for (int kc = 0; kc < 8; kc++) {
        __syncthreads();
        {   // A chunk: 64 rows x 32 halves, converted from fp32 x in-flight
            const float* xs = x + (row_base + arow) * FIN + kc * 32 + ac;
            const float4 v0 = *(const float4*)xs;
            const float4 v1 = *(const float4*)(xs + 4);
            const float f[8] = {v0.x, v0.y, v0.z, v0.w, v1.x, v1.y, v1.z, v1.w};
            __half h[8], l[8];
            #pragma unroll
            for (int i = 0; i < 8; i++) {
                h[i] = __float2half(f[i]);
                l[i] = __float2half(f[i] - __half2float(h[i]));
            }
            __half2 hp[4], lp[4];
            #pragma unroll
            for (int i = 0; i < 4; i++) {
                hp[i] = __halves2half2(h[2 * i], h[2 * i + 1]);
                lp[i] = __halves2half2(l[2 * i], l[2 * i + 1]);
            }
            *(int4*)(Ah + arow * APAD + ac) = *(const int4*)hp;
            *(int4*)(Al + arow * APAD + ac) = *(const int4*)lp;
        }
        {   // B chunk: W rows kc*32..+32 (fp32 [k][n]) -> fp16 smem [k][n]
            #pragma unroll
            for (int u = 0; u < 8; u++) {
                const int li = tid + u * 256;        // 0..2047 float4s
                const int br = li >> 6;              // k row 0..31
                const int bc = (li & 63) * 4;        // n col
                const float4 v = *(const float4*)(W + (size_t)(kc * 32 + br) * FOUT + bc);
                const __half2 p0 = __floats2half2_rn(v.x, v.y);
                const __half2 p1 = __floats2half2_rn(v.z, v.w);
                uint2 pk;
                pk.x = *(const uint32_t*)&p0;
                pk.y = *(const uint32_t*)&p1;
                *(uint2*)(Bs + br * BPAD + bc) = pk;
            }
        }
        __syncthreads();
        #pragma unroll
        for (int ks = 0; ks < 2; ks++) {
            const int kk = ks * 16;
            const int ar0 = (m0 + g) * APAD + kk + 2 * q;
            const int ar1 = (m0 + g + 8) * APAD + kk + 2 * q;
            uint32_t ah[4], alr[4];
            ah[0] = *(const uint32_t*)(Ah + ar0);
            ah[1] = *(const uint32_t*)(Ah + ar1);
            ah[2] = *(const uint32_t*)(Ah + ar0 + 8);
            ah[3] = *(const uint32_t*)(Ah + ar1 + 8);
            alr[0] = *(const uint32_t*)(Al + ar0);
            alr[1] = *(const uint32_t*)(Al + ar1);
            alr[2] = *(const uint32_t*)(Al + ar0 + 8);
            alr[3] = *(const uint32_t*)(Al + ar1 + 8);
            // ldmatrix row base for this warp/ks: row = kk + l16, col = n0
            const uint32_t baddr0 = bbase + (uint32_t)(((kk + l16) * BPAD + n0) * 2);
            #pragma unroll
            for (int nt = 0; nt < 16; nt++) {
                uint32_t b0, b1;
                asm volatile(
                    "ldmatrix.sync.aligned.m8n8.x2.trans.shared.b16 {%0,%1}, [%2];"
                    : "=r"(b0), "=r"(b1) : "r"(baddr0 + (uint32_t)(nt * 16)));
                uint32_t bh[2] = {b0, b1};
                mma16816(acc[nt], ah,  bh);
                mma16816(acc[nt], alr, bh);
            }
        }
    }
    __syncthreads();
    // stage accumulators to smem (fp32)
    #pragma unroll
    for (int nt = 0; nt < 16; nt++) {
        const int col = n0 + nt * 8 + 2 * q;
        *(float2*)(hs + (m0 + g) * FOUT + col)     = make_float2(acc[nt][0], acc[nt][1]);
        *(float2*)(hs + (m0 + g + 8) * FOUT + col) = make_float2(acc[nt][2], acc[nt][3]);
    }
    __syncthreads();

    // LayerNorm + logits: one warp per row, 8 rows per warp
    for (int rr = wid; rr < 64; rr += 8) {
        float v[8];
        float s = 0.0f, ss = 0.0f;
        #pragma unroll
        for (int k = 0; k < 8; k++) {
            v[k] = hs[rr * FOUT + lane + 32 * k];
            s += v[k];
            ss = fmaf(v[k], v[k], ss);
        }
        #pragma unroll
        for (int o = 16; o; o >>= 1) {
            s  += __shfl_xor_sync(0xffffffffu, s,  o);
            ss += __shfl_xor_sync(0xffffffffu, ss, o);
        }
        const float mu = s * (1.0f / FOUT);
        const float var = ss * (1.0f / FOUT) - mu * mu;
        const float rstd = rsqrtf(var + 1e-5f);

        const size_t row = row_base + rr;
        float es[4] = {0, 0, 0, 0}, ed[4] = {0, 0, 0, 0};
        #pragma unroll
        for (int k = 0; k < 8; k++) {
            const int col = lane + 32 * k;
            const float n = fmaf((v[k] - mu) * rstd, gamma[col], beta[col]);
            g_h16[row * FOUT + col] = __float2half(n);
            const int hh = k >> 1;
            const int d = lane + 32 * (k & 1);
            es[hh] = fmaf(n, aw[d], es[hh]);
            ed[hh] = fmaf(n, aw[DD + d], ed[hh]);
        }
        #pragma unroll
        for (int o = 16; o; o >>= 1) {
            #pragma unroll
            for (int hh = 0; hh < 4; hh++) {
                es[hh] += __shfl_xor_sync(0xffffffffu, es[hh], o);
                ed[hh] += __shfl_xor_sync(0xffffffffu, ed[hh], o);
            }
        }
        if (lane == 0) {
            #pragma unroll
            for (int hh = 0; hh < 4; hh++) {
                g_ei[row * HH + hh] = es[hh];
                g_ej[row * HH + hh] = ed[hh];
            }
        }
    }
}

// ---------------------------------------------------------------------------
// Kernel 2: block-per-row sparse softmax+gather, single-pass exp (R7-exact).
// ---------------------------------------------------------------------------
__global__ void __launch_bounds__(256) attn_kernel(
    const float* __restrict__ adj, float* __restrict__ out)
{
    __shared__ int    nbr[NN];
    __shared__ float  sc[NN * HH];
    __shared__ float  redg[7 * 32 * 8];
    __shared__ int   wsum[8];
    __shared__ int   woff[8];
    __shared__ int   Ktot_s;
    __shared__ float red[8 * HH];
    __shared__ float sms[HH];

    const int tid = threadIdx.x;
    const int lane = tid & 31, wid = tid >> 5;
    const size_t bi = blockIdx.x;
    const size_t b  = bi >> 10;

    // ---- ordered neighbor compaction ----
    const float4 av = ((const float4*)(adj + bi * NN))[tid];
    const int m0 = (av.x != 0.0f), m1 = (av.y != 0.0f), m2 = (av.z != 0.0f), m3 = (av.w != 0.0f);
    int cnt = m0 + m1 + m2 + m3;
    int pre = cnt;
    #pragma unroll
    for (int o = 1; o < 32; o <<= 1) {
        int t = __shfl_up_sync(0xffffffffu, pre, o);
        if (lane >= o) pre += t;
    }
    if (lane == 31) wsum[wid] = pre;
    __syncthreads();
    if (tid == 0) {
        int acc = 0;
        #pragma unroll
        for (int w = 0; w < 8; w++) { woff[w] = acc; acc += wsum[w]; }
        Ktot_s = acc;
    }
    __syncthreads();
    {
        int p = woff[wid] + pre - cnt;
        const int j0 = tid * 4;
        if (m0) nbr[p++] = j0;
        if (m1) nbr[p++] = j0 + 1;
        if (m2) nbr[p++] = j0 + 2;
        if (m3) nbr[p++] = j0 + 3;
    }
    __syncthreads();
    const int K = Ktot_s;

    // ---- fused scores: w = exp(leakyrelu(e_i + e_j)), accumulate sums ----
    float ei0, ei1, ei2, ei3;
    {
        const float4 e4 = ((const float4*)g_ei)[bi];
        ei0 = e4.x; ei1 = e4.y; ei2 = e4.z; ei3 = e4.w;
    }
    const float4* ej4 = (const float4*)g_ej + b * NN;
    float4* sc4 = (float4*)sc;
    float ls0 = 0, ls1 = 0, ls2 = 0, ls3 = 0;
    for (int nn = tid; nn < K; nn += 256) {
        const int j = nbr[nn];
        const float4 e4 = ej4[j];
        float t0 = ei0 + e4.x, t1 = ei1 + e4.y, t2 = ei2 + e4.z, t3 = ei3 + e4.w;
        t0 = t0 > 0.0f ? t0 : 0.2f * t0;
        t1 = t1 > 0.0f ? t1 : 0.2f * t1;
        t2 = t2 > 0.0f ? t2 : 0.2f * t2;
        t3 = t3 > 0.0f ? t3 : 0.2f * t3;
        const float w0 = __expf(t0), w1 = __expf(t1), w2 = __expf(t2), w3 = __expf(t3);
        sc4[nn] = make_float4(w0, w1, w2, w3);
        ls0 += w0; ls1 += w1; ls2 += w2; ls3 += w3;
    }
    #pragma unroll
    for (int o = 16; o; o >>= 1) {
        ls0 += __shfl_xor_sync(0xffffffffu, ls0, o);
        ls1 += __shfl_xor_sync(0xffffffffu, ls1, o);
        ls2 += __shfl_xor_sync(0xffffffffu, ls2, o);
        ls3 += __shfl_xor_sync(0xffffffffu, ls3, o);
    }
    if (lane == 0) {
        red[wid * 4 + 0] = ls0;
        red[wid * 4 + 1] = ls1;
        red[wid * 4 + 2] = ls2;
        red[wid * 4 + 3] = ls3;
    }
    __syncthreads();
    if (tid < 4) {
        float s = 0.0f;
        #pragma unroll
        for (int w = 0; w < 8; w++) s += red[w * 4 + tid];
        sms[tid] = s;
    }
    __syncthreads();

    // ---- gather-accumulate: 32 uint4 col-groups (8 halves) x 8 slices ----
    const int cg = tid & 31;
    const int sl = tid >> 5;
    const int hh = cg >> 3;
    const __half* hb = g_h16 + b * NN * FOUT;
    const float* wts = sc + hh;

    float a0 = 0, a1 = 0, a2 = 0, a3 = 0, a4 = 0, a5 = 0, a6 = 0, a7 = 0;
    for (int nn = sl; nn < K; nn += 8) {
        const int j = nbr[nn];
        const float w = wts[nn * 4];
        const uint4 hv = ((const uint4*)(hb + (size_t)j * FOUT))[cg];
        const half2* hp = (const half2*)&hv;
        const float2 f0 = __half22float2(hp[0]);
        const float2 f1 = __half22float2(hp[1]);
        const float2 f2 = __half22float2(hp[2]);
        const float2 f3 = __half22float2(hp[3]);
        a0 = fmaf(w, f0.x, a0); a1 = fmaf(w, f0.y, a1);
        a2 = fmaf(w, f1.x, a2); a3 = fmaf(w, f1.y, a3);
        a4 = fmaf(w, f2.x, a4); a5 = fmaf(w, f2.y, a5);
        a6 = fmaf(w, f3.x, a6); a7 = fmaf(w, f3.y, a7);
    }
    if (sl != 0) {
        float* rp = redg + ((sl - 1) * 32 + cg) * 8;
        ((float4*)rp)[0] = make_float4(a0, a1, a2, a3);
        ((float4*)rp)[1] = make_float4(a4, a5, a6, a7);
    }
    __syncthreads();
    if (sl == 0) {
        #pragma unroll
        for (int s = 0; s < 7; s++) {
            const float* rp = redg + (s * 32 + cg) * 8;
            const float4 p0 = ((const float4*)rp)[0];
            const float4 p1 = ((const float4*)rp)[1];
            a0 += p0.x; a1 += p0.y; a2 += p0.z; a3 += p0.w;
            a4 += p1.x; a5 += p1.y; a6 += p1.z; a7 += p1.w;
        }
        const float inv = 1.0f / sms[hh];
        float4* op = (float4*)(out + bi * FOUT + cg * 8);
        op[0] = make_float4(a0 * inv, a1 * inv, a2 * inv, a3 * inv);
        op[1] = make_float4(a4 * inv, a5 * inv, a6 * inv, a7 * inv);
    }
}

extern "C" void kernel_launch(void* const* d_in, const int* in_sizes, int n_in,
                              void* d_out, int out_size)
{
    const float* x     = (const float*)d_in[0];
    const float* adj   = (const float*)d_in[1];
    const float* W     = (const float*)d_in[2];
    const float* gamma = (const float*)d_in[3];
    const float* beta  = (const float*)d_in[4];
    const float* a     = (const float*)d_in[5];
    float* out = (float*)d_out;

    const int dsm = 64 * FOUT * sizeof(float);   // 64KB union (>= GEMM buffers)
    cudaFuncSetAttribute(gemm_ln_tc, cudaFuncAttributeMaxDynamicSharedMemorySize, dsm);

    gemm_ln_tc<<<(BB * NN) / 64, 256, dsm>>>(x, W, gamma, beta, a);
    attn_kernel<<<BB * NN, 256>>>(adj, out);
}